// round 15
// baseline (speedup 1.0000x reference)
#include <cuda_runtime.h>
#include <cuda_fp16.h>

#define NN 100000
#define NE 1600000
#define C  128
#define NCLS 40
#define NB_SCAN 98   // ceil(NN/1024)

// ---------------- scratch ----------------------------------------------------
__device__ int   g_deg_out[NN];
__device__ int   g_deg_in[NN];
__device__ int   g_rowptr[NN + 1];
__device__ int   g_tick[NE];
__device__ int   g_col[NE];
__device__ int   g_blocksum[NB_SCAN];
__device__ int   g_blockoff[NB_SCAN];
__device__ float g_nsrc[NN];
__device__ float g_ndst[NN];
__device__ float g_A[(size_t)NN * C];    // fp32 aggregation results
__device__ uint2 g_G[(size_t)NN * 32];   // fp16 gather source (layers 0,1 input)
__device__ uint2 g_G2[(size_t)NN * 32];  // fp16 gather source (layer 2 input)

// ---------------- packed f32x2 helpers ---------------------------------------
__device__ __forceinline__ unsigned long long pk2(float a, float b) {
    unsigned long long r; asm("mov.b64 %0,{%1,%2};" : "=l"(r) : "f"(a), "f"(b)); return r;
}
__device__ __forceinline__ unsigned long long fma2(unsigned long long a, unsigned long long b,
                                                   unsigned long long c) {
    unsigned long long d;
    asm("fma.rn.f32x2 %0,%1,%2,%3;" : "=l"(d) : "l"(a), "l"(b), "l"(c));
    return d;
}
__device__ __forceinline__ float2 upk2(unsigned long long v) {
    float2 r; asm("mov.b64 {%0,%1},%2;" : "=f"(r.x), "=f"(r.y) : "l"(v)); return r;
}

// ---------------- degree + ticket ---------------------------------------------
__global__ void degree_kernel(const int* __restrict__ src, const int* __restrict__ dst) {
    int e = blockIdx.x * blockDim.x + threadIdx.x;
    if (e < NE) {
        atomicAdd(&g_deg_out[src[e]], 1);
        g_tick[e] = atomicAdd(&g_deg_in[dst[e]], 1);
    }
}

// prescale + rowptr-fix (scan3 folded into c==0 lane)
__global__ void prescale_kernel(const float* __restrict__ x) {
    int i = blockIdx.x * blockDim.x + threadIdx.x;
    if (i >= NN * 32) return;
    int n = i >> 5, c = i & 31;
    float s = rsqrtf(fmaxf((float)g_deg_out[n], 1.f));
    if (c == 0) {
        g_nsrc[n] = s;
        g_ndst[n] = rsqrtf(fmaxf((float)g_deg_in[n], 1.f));
        g_rowptr[n] += g_blockoff[n >> 10];     // scan3 fold
    }
    float4 v = *(const float4*)(x + (size_t)n * C + c * 4);
    __half2 h0 = __floats2half2_rn(v.x * s, v.y * s);
    __half2 h1 = __floats2half2_rn(v.z * s, v.w * s);
    uint2 o; o.x = *(unsigned*)&h0; o.y = *(unsigned*)&h1;
    g_G[(size_t)n * 32 + c] = o;
}

__global__ void scan1_kernel() {
    __shared__ int wsums[32];
    int tid = threadIdx.x, lane = tid & 31, wid = tid >> 5;
    int i = blockIdx.x * 1024 + tid;
    int v = (i < NN) ? g_deg_in[i] : 0;
    int xv = v;
    #pragma unroll
    for (int o = 1; o < 32; o <<= 1) {
        int y = __shfl_up_sync(0xffffffffu, xv, o);
        if (lane >= o) xv += y;
    }
    if (lane == 31) wsums[wid] = xv;
    __syncthreads();
    if (wid == 0) {
        int wv = wsums[lane];
        #pragma unroll
        for (int o = 1; o < 32; o <<= 1) {
            int y = __shfl_up_sync(0xffffffffu, wv, o);
            if (lane >= o) wv += y;
        }
        wsums[lane] = wv;
    }
    __syncthreads();
    int incl = xv + (wid ? wsums[wid - 1] : 0);
    if (i < NN) g_rowptr[i] = incl - v;
    if (tid == 1023) g_blocksum[blockIdx.x] = incl;
}

__global__ void scan2_kernel() {
    __shared__ int s[128];
    int t = threadIdx.x;
    int v = (t < NB_SCAN) ? g_blocksum[t] : 0;
    s[t] = v;
    __syncthreads();
    #pragma unroll
    for (int o = 1; o < 128; o <<= 1) {
        int y = (t >= o) ? s[t - o] : 0;
        __syncthreads();
        s[t] += y;
        __syncthreads();
    }
    if (t < NB_SCAN) g_blockoff[t] = s[t] - v;
    if (t == 127) g_rowptr[NN] = s[127];
}

// scatter: atomic-free; uses unfixed rowptr + blockoff (runs before prescale fix)
__global__ void scatter_kernel(const int* __restrict__ src, const int* __restrict__ dst) {
    int e = blockIdx.x * blockDim.x + threadIdx.x;
    if (e < NE) {
        int d = dst[e];
        int pos = g_rowptr[d] + g_blockoff[d >> 10] + g_tick[e];
        g_col[pos] = src[e];
    }
}

// ---------------- agg core: 16 loads in flight, pairwise fp16 -----------------
__device__ __forceinline__ void acc_pair(uint2 ua, uint2 ub,
                                         float& a0, float& a1, float& a2, float& a3) {
    __half2 px = __hadd2(*(__half2*)&ua.x, *(__half2*)&ub.x);
    __half2 py = __hadd2(*(__half2*)&ua.y, *(__half2*)&ub.y);
    float2 f0 = __half22float2(px);
    float2 f1 = __half22float2(py);
    a0 += f0.x; a1 += f0.y; a2 += f1.x; a3 += f1.y;
}
__device__ __forceinline__ void acc_one(uint2 u,
                                        float& a0, float& a1, float& a2, float& a3) {
    float2 f0 = __half22float2(*(__half2*)&u.x);
    float2 f1 = __half22float2(*(__half2*)&u.y);
    a0 += f0.x; a1 += f0.y; a2 += f1.x; a3 += f1.y;
}

__device__ __forceinline__ void agg_row(const uint2* __restrict__ G, int w, int lane,
                                        float& a0, float& a1, float& a2, float& a3) {
    int e = g_rowptr[w], end = g_rowptr[w + 1];
    const int* __restrict__ col = g_col;
    for (; e + 15 < end; e += 16) {
        int s[16];
        #pragma unroll
        for (int q = 0; q < 16; q++) s[q] = col[e + q];
        uint2 u[16];
        #pragma unroll
        for (int q = 0; q < 16; q++) u[q] = G[(size_t)s[q] * 32 + lane];
        #pragma unroll
        for (int q = 0; q < 16; q += 2) acc_pair(u[q], u[q + 1], a0, a1, a2, a3);
    }
    for (; e + 7 < end; e += 8) {
        int s0 = col[e],     s1 = col[e + 1], s2 = col[e + 2], s3 = col[e + 3];
        int s4 = col[e + 4], s5 = col[e + 5], s6 = col[e + 6], s7 = col[e + 7];
        uint2 u0 = G[(size_t)s0 * 32 + lane];
        uint2 u1 = G[(size_t)s1 * 32 + lane];
        uint2 u2 = G[(size_t)s2 * 32 + lane];
        uint2 u3 = G[(size_t)s3 * 32 + lane];
        uint2 u4 = G[(size_t)s4 * 32 + lane];
        uint2 u5 = G[(size_t)s5 * 32 + lane];
        uint2 u6 = G[(size_t)s6 * 32 + lane];
        uint2 u7 = G[(size_t)s7 * 32 + lane];
        acc_pair(u0, u1, a0, a1, a2, a3);
        acc_pair(u2, u3, a0, a1, a2, a3);
        acc_pair(u4, u5, a0, a1, a2, a3);
        acc_pair(u6, u7, a0, a1, a2, a3);
    }
    for (; e + 1 < end; e += 2) {
        int s0 = col[e], s1 = col[e + 1];
        uint2 u0 = G[(size_t)s0 * 32 + lane];
        uint2 u1 = G[(size_t)s1 * 32 + lane];
        acc_pair(u0, u1, a0, a1, a2, a3);
    }
    if (e < end) {
        uint2 u = G[(size_t)col[e] * 32 + lane];
        acc_one(u, a0, a1, a2, a3);
    }
}

// standalone agg: G (param) -> g_A
__global__ void __launch_bounds__(256) agg_kernel(const uint2* __restrict__ G) {
    int w = blockIdx.x * 8 + (threadIdx.x >> 5);
    if (w >= NN) return;
    int lane = threadIdx.x & 31;
    float a0 = 0.f, a1 = 0.f, a2 = 0.f, a3 = 0.f;
    agg_row(G, w, lane, a0, a1, a2, a3);
    float4 r; r.x = a0; r.y = a1; r.z = a2; r.w = a3;
    *(float4*)(g_A + (size_t)w * C + lane * 4) = r;
}

// ---------------- layer-1 transform: split, 64 nodes/block, smem weights ------
__global__ void __launch_bounds__(256) t1_kernel(const float* __restrict__ W1,
                                                 const float* __restrict__ b1,
                                                 float* __restrict__ f1out) {
    __shared__ float Ws[4 * 1032];
    int t = threadIdx.x;
    for (int i = t; i < 4096; i += 256) {
        int b = i >> 10, r = i & 1023;
        Ws[b * 1032 + r] = W1[i];
    }
    __syncthreads();
    int n = blockIdx.x * 64 + (t >> 2);
    int b = t & 3;
    if (n >= NN) return;
    float in[32];
    const float* arow = g_A + (size_t)n * C + b * 32;
    #pragma unroll
    for (int q = 0; q < 8; q++) {
        float4 v = *(const float4*)(arow + q * 4);
        in[q * 4] = v.x; in[q * 4 + 1] = v.y; in[q * 4 + 2] = v.z; in[q * 4 + 3] = v.w;
    }
    float acc[32];
    #pragma unroll
    for (int jq = 0; jq < 32; jq++) acc[jq] = 0.f;
    #pragma unroll
    for (int kk = 0; kk < 32; kk++) {
        float a = in[kk];
        const float* wr = &Ws[b * 1032 + kk * 32];
        #pragma unroll
        for (int q = 0; q < 8; q++) {
            float4 w = *(const float4*)(wr + q * 4);
            acc[q * 4]     = fmaf(a, w.x, acc[q * 4]);
            acc[q * 4 + 1] = fmaf(a, w.y, acc[q * 4 + 1]);
            acc[q * 4 + 2] = fmaf(a, w.z, acc[q * 4 + 2]);
            acc[q * 4 + 3] = fmaf(a, w.w, acc[q * 4 + 3]);
        }
    }
    float nd = g_ndst[n], ns = g_nsrc[n];
    const float* bb = b1 + b * 32;
    float* fo = f1out + ((size_t)b * NN + n) * 32;
    #pragma unroll
    for (int q = 0; q < 8; q++) {
        float4 bv = *(const float4*)(bb + q * 4);
        float4 f;
        f.x = fmaf(acc[q * 4],     nd, bv.x);
        f.y = fmaf(acc[q * 4 + 1], nd, bv.y);
        f.z = fmaf(acc[q * 4 + 2], nd, bv.z);
        f.w = fmaf(acc[q * 4 + 3], nd, bv.w);
        *(float4*)(fo + q * 4) = f;
        __half2 g0 = __floats2half2_rn(fmaxf(f.x, 0.f) * ns, fmaxf(f.y, 0.f) * ns);
        __half2 g1 = __floats2half2_rn(fmaxf(f.z, 0.f) * ns, fmaxf(f.w, 0.f) * ns);
        uint2 o; o.x = *(unsigned*)&g0; o.y = *(unsigned*)&g1;
        g_G2[(size_t)n * 32 + b * 8 + q] = o;
    }
}

// ---------------- output transform (64 nodes/block, smem weights) -------------
__global__ void __launch_bounds__(256) t2_kernel(const float* __restrict__ Wout,
                                                 const float* __restrict__ bout,
                                                 float* __restrict__ outp) {
    __shared__ float Ws[4 * 1288];
    int t = threadIdx.x;
    for (int i = t; i < 4 * 1280; i += 256) {
        int b = i / 1280, r = i % 1280;
        Ws[b * 1288 + r] = Wout[i];
    }
    __syncthreads();
    int n = blockIdx.x * 64 + (t >> 2);
    int b = t & 3;
    if (n >= NN) return;
    float in[32];
    const float* arow = g_A + (size_t)n * C + b * 32;
    #pragma unroll
    for (int q = 0; q < 8; q++) {
        float4 v = *(const float4*)(arow + q * 4);
        in[q * 4] = v.x; in[q * 4 + 1] = v.y; in[q * 4 + 2] = v.z; in[q * 4 + 3] = v.w;
    }
    float acc[40];
    #pragma unroll
    for (int jq = 0; jq < 40; jq++) acc[jq] = 0.f;
    #pragma unroll
    for (int kk = 0; kk < 32; kk++) {
        float a = in[kk];
        const float* wr = &Ws[b * 1288 + kk * 40];
        #pragma unroll
        for (int q = 0; q < 10; q++) {
            float4 w = *(const float4*)(wr + q * 4);
            acc[q * 4]     = fmaf(a, w.x, acc[q * 4]);
            acc[q * 4 + 1] = fmaf(a, w.y, acc[q * 4 + 1]);
            acc[q * 4 + 2] = fmaf(a, w.z, acc[q * 4 + 2]);
            acc[q * 4 + 3] = fmaf(a, w.w, acc[q * 4 + 3]);
        }
    }
    float nd = g_ndst[n];
    const float* bb = bout + b * 40;
    float* oo = outp + ((size_t)b * NN + n) * 40;
    #pragma unroll
    for (int q = 0; q < 10; q++) {
        float4 bv = *(const float4*)(bb + q * 4);
        float4 f;
        f.x = fmaf(acc[q * 4],     nd, bv.x);
        f.y = fmaf(acc[q * 4 + 1], nd, bv.y);
        f.z = fmaf(acc[q * 4 + 2], nd, bv.z);
        f.w = fmaf(acc[q * 4 + 3], nd, bv.w);
        *(float4*)(oo + q * 4) = f;
    }
}

// ---------------- layer 0: [128 x 128] @ [128 x 128], 512 thr, f32x2 ---------
#define T0_PAD 132
#define T0_SMEM ((128 * 128 + 128 * T0_PAD) * 4)
__global__ void __launch_bounds__(512) t0_kernel(const float* __restrict__ W0,
                                                 const float* __restrict__ b0,
                                                 float* __restrict__ f0out) {
    extern __shared__ float sm[];
    float* Ws = sm;
    float* As = sm + 128 * 128;
    int t = threadIdx.x;
    int node0 = blockIdx.x * 128;
    for (int i = t; i < 4 * 128 * 32; i += 512) {
        int b = i >> 12, k = (i >> 5) & 127, j = i & 31;
        Ws[k * 128 + b * 32 + j] = W0[i];
    }
    for (int i = t; i < 128 * 128; i += 512) {
        int k = i & 127, n = i >> 7;
        int gn = node0 + n;
        As[k * T0_PAD + n] = (gn < NN) ? g_A[(size_t)gn * C + k] : 0.f;
    }
    __syncthreads();

    int cH = (t & 15) * 4;
    int nB = (t >> 4) * 4;
    unsigned long long acc[4][4];
    #pragma unroll
    for (int n = 0; n < 4; n++)
        #pragma unroll
        for (int p = 0; p < 4; p++) acc[n][p] = 0ull;

    #pragma unroll 4
    for (int k = 0; k < 128; k++) {
        float4 wa = *(const float4*)&Ws[k * 128 + cH];
        float4 wb = *(const float4*)&Ws[k * 128 + cH + 64];
        unsigned long long w0 = pk2(wa.x, wa.y), w1 = pk2(wa.z, wa.w);
        unsigned long long w2 = pk2(wb.x, wb.y), w3 = pk2(wb.z, wb.w);
        float4 A0 = *(const float4*)&As[k * T0_PAD + nB];
        float av[4] = {A0.x, A0.y, A0.z, A0.w};
        #pragma unroll
        for (int n = 0; n < 4; n++) {
            unsigned long long ap = pk2(av[n], av[n]);
            acc[n][0] = fma2(ap, w0, acc[n][0]);
            acc[n][1] = fma2(ap, w1, acc[n][1]);
            acc[n][2] = fma2(ap, w2, acc[n][2]);
            acc[n][3] = fma2(ap, w3, acc[n][3]);
        }
    }

    int bA = cH >> 5, jA = cH & 31;
    int cB = cH + 64;
    int bB = cB >> 5, jB = cB & 31;
    float4 biasA = *(const float4*)&b0[cH];
    float4 biasB = *(const float4*)&b0[cB];
    #pragma unroll
    for (int n = 0; n < 4; n++) {
        int gn = node0 + nB + n;
        if (gn >= NN) break;
        float nd = g_ndst[gn], ns = g_nsrc[gn];
        float2 p0 = upk2(acc[n][0]), p1 = upk2(acc[n][1]);
        float2 p2 = upk2(acc[n][2]), p3 = upk2(acc[n][3]);
        float4 fa, fb;
        fa.x = fmaf(p0.x, nd, biasA.x); fa.y = fmaf(p0.y, nd, biasA.y);
        fa.z = fmaf(p1.x, nd, biasA.z); fa.w = fmaf(p1.y, nd, biasA.w);
        fb.x = fmaf(p2.x, nd, biasB.x); fb.y = fmaf(p2.y, nd, biasB.y);
        fb.z = fmaf(p3.x, nd, biasB.z); fb.w = fmaf(p3.y, nd, biasB.w);
        *(float4*)&f0out[((size_t)bA * NN + gn) * 32 + jA] = fa;
        *(float4*)&f0out[((size_t)bB * NN + gn) * 32 + jB] = fb;
        __half2 ga0 = __floats2half2_rn(fmaxf(fa.x, 0.f) * ns, fmaxf(fa.y, 0.f) * ns);
        __half2 ga1 = __floats2half2_rn(fmaxf(fa.z, 0.f) * ns, fmaxf(fa.w, 0.f) * ns);
        __half2 gb0 = __floats2half2_rn(fmaxf(fb.x, 0.f) * ns, fmaxf(fb.y, 0.f) * ns);
        __half2 gb1 = __floats2half2_rn(fmaxf(fb.z, 0.f) * ns, fmaxf(fb.w, 0.f) * ns);
        uint2 oa; oa.x = *(unsigned*)&ga0; oa.y = *(unsigned*)&ga1;
        uint2 ob; ob.x = *(unsigned*)&gb0; ob.y = *(unsigned*)&gb1;
        g_G[(size_t)gn * 32 + (cH >> 2)] = oa;
        g_G[(size_t)gn * 32 + (cB >> 2)] = ob;
    }
}

// ---------------- launch --------------------------------------------------------
extern "C" void kernel_launch(void* const* d_in, const int* in_sizes, int n_in,
                              void* d_out, int out_size) {
    const float* x    = (const float*)d_in[0];
    const int*   src  = (const int*)d_in[1];
    const int*   dst  = (const int*)d_in[2];
    const float* W0   = (const float*)d_in[3];
    const float* b0   = (const float*)d_in[4];
    const float* W1   = (const float*)d_in[5];
    const float* b1   = (const float*)d_in[6];
    const float* Wout = (const float*)d_in[7];
    const float* bout = (const float*)d_in[8];

    float* outp = (float*)d_out;
    float* f0p  = outp + (size_t)4 * NN * NCLS;
    float* f1p  = f0p + (size_t)4 * NN * 32;

    cudaFuncSetAttribute(t0_kernel, cudaFuncAttributeMaxDynamicSharedMemorySize, T0_SMEM);

    void* p_deg_out; cudaGetSymbolAddress(&p_deg_out, g_deg_out);
    void* p_deg_in;  cudaGetSymbolAddress(&p_deg_in,  g_deg_in);
    void* p_G;       cudaGetSymbolAddress(&p_G,       g_G);
    void* p_G2;      cudaGetSymbolAddress(&p_G2,      g_G2);
    cudaMemsetAsync(p_deg_out, 0, NN * sizeof(int));
    cudaMemsetAsync(p_deg_in,  0, NN * sizeof(int));

    int nb_edges = (NE + 255) / 256;
    int nb_agg   = (NN + 7) / 8;
    int nb_t64   = (NN + 63) / 64;
    int nb_t128  = (NN + 127) / 128;
    int nb_pre   = (NN * 32 + 255) / 256;

    degree_kernel<<<nb_edges, 256>>>(src, dst);           // 0 (writes tickets)
    scan1_kernel<<<NB_SCAN, 1024>>>();                    // 1
    scan2_kernel<<<1, 128>>>();                           // 2
    scatter_kernel<<<nb_edges, 256>>>(src, dst);          // 3 (atomic-free)
    prescale_kernel<<<nb_pre, 256>>>(x);                  // 4 (+rowptr fix)

    agg_kernel<<<nb_agg, 256>>>((const uint2*)p_G);       // layer 0: G -> g_A
    t0_kernel<<<nb_t128, 512, T0_SMEM>>>(W0, b0, f0p);    // g_A -> f0, g_G
    agg_kernel<<<nb_agg, 256>>>((const uint2*)p_G);       // layer 1: G -> g_A
    t1_kernel<<<nb_t64, 256>>>(W1, b1, f1p);              // g_A -> f1, g_G2
    agg_kernel<<<nb_agg, 256>>>((const uint2*)p_G2);      // layer 2: G2 -> g_A
    t2_kernel<<<nb_t64, 256>>>(Wout, bout, outp);         // g_A -> logits
}

// round 16
// speedup vs baseline: 1.1036x; 1.1036x over previous
#include <cuda_runtime.h>
#include <cuda_fp16.h>

#define NN 100000
#define NE 1600000
#define C  128
#define NCLS 40
#define NB_SCAN 98   // ceil(NN/1024)

// ---------------- scratch ----------------------------------------------------
__device__ int   g_deg_out[NN];
__device__ int   g_deg_in[NN];
__device__ int   g_rowptr[NN + 1];
__device__ int   g_tick[NE];
__device__ int   g_col[NE];
__device__ int   g_blocksum[NB_SCAN];
__device__ int   g_blockoff[NB_SCAN];
__device__ float g_nsrc[NN];
__device__ float g_ndst[NN];
__device__ float g_A[(size_t)NN * C];    // fp32 aggregation results
__device__ uint2 g_G[(size_t)NN * 32];   // fp16 gather source (layers 0,1 input)
__device__ uint2 g_G2[(size_t)NN * 32];  // fp16 gather source (layer 2 input)

// ---------------- packed f32x2 helpers ---------------------------------------
__device__ __forceinline__ unsigned long long pk2(float a, float b) {
    unsigned long long r; asm("mov.b64 %0,{%1,%2};" : "=l"(r) : "f"(a), "f"(b)); return r;
}
__device__ __forceinline__ unsigned long long fma2(unsigned long long a, unsigned long long b,
                                                   unsigned long long c) {
    unsigned long long d;
    asm("fma.rn.f32x2 %0,%1,%2,%3;" : "=l"(d) : "l"(a), "l"(b), "l"(c));
    return d;
}
__device__ __forceinline__ float2 upk2(unsigned long long v) {
    float2 r; asm("mov.b64 {%0,%1},%2;" : "=f"(r.x), "=f"(r.y) : "l"(v)); return r;
}

// ---------------- degree + ticket ---------------------------------------------
__global__ void degree_kernel(const int* __restrict__ src, const int* __restrict__ dst) {
    int e = blockIdx.x * blockDim.x + threadIdx.x;
    if (e < NE) {
        atomicAdd(&g_deg_out[src[e]], 1);
        g_tick[e] = atomicAdd(&g_deg_in[dst[e]], 1);
    }
}

// prescale + rowptr-fix (scan3 folded into c==0 lane)
__global__ void prescale_kernel(const float* __restrict__ x) {
    int i = blockIdx.x * blockDim.x + threadIdx.x;
    if (i >= NN * 32) return;
    int n = i >> 5, c = i & 31;
    float s = rsqrtf(fmaxf((float)g_deg_out[n], 1.f));
    if (c == 0) {
        g_nsrc[n] = s;
        g_ndst[n] = rsqrtf(fmaxf((float)g_deg_in[n], 1.f));
        g_rowptr[n] += g_blockoff[n >> 10];     // scan3 fold
    }
    float4 v = *(const float4*)(x + (size_t)n * C + c * 4);
    __half2 h0 = __floats2half2_rn(v.x * s, v.y * s);
    __half2 h1 = __floats2half2_rn(v.z * s, v.w * s);
    uint2 o; o.x = *(unsigned*)&h0; o.y = *(unsigned*)&h1;
    g_G[(size_t)n * 32 + c] = o;
}

__global__ void scan1_kernel() {
    __shared__ int wsums[32];
    int tid = threadIdx.x, lane = tid & 31, wid = tid >> 5;
    int i = blockIdx.x * 1024 + tid;
    int v = (i < NN) ? g_deg_in[i] : 0;
    int xv = v;
    #pragma unroll
    for (int o = 1; o < 32; o <<= 1) {
        int y = __shfl_up_sync(0xffffffffu, xv, o);
        if (lane >= o) xv += y;
    }
    if (lane == 31) wsums[wid] = xv;
    __syncthreads();
    if (wid == 0) {
        int wv = wsums[lane];
        #pragma unroll
        for (int o = 1; o < 32; o <<= 1) {
            int y = __shfl_up_sync(0xffffffffu, wv, o);
            if (lane >= o) wv += y;
        }
        wsums[lane] = wv;
    }
    __syncthreads();
    int incl = xv + (wid ? wsums[wid - 1] : 0);
    if (i < NN) g_rowptr[i] = incl - v;
    if (tid == 1023) g_blocksum[blockIdx.x] = incl;
}

__global__ void scan2_kernel() {
    __shared__ int s[128];
    int t = threadIdx.x;
    int v = (t < NB_SCAN) ? g_blocksum[t] : 0;
    s[t] = v;
    __syncthreads();
    #pragma unroll
    for (int o = 1; o < 128; o <<= 1) {
        int y = (t >= o) ? s[t - o] : 0;
        __syncthreads();
        s[t] += y;
        __syncthreads();
    }
    if (t < NB_SCAN) g_blockoff[t] = s[t] - v;
    if (t == 127) g_rowptr[NN] = s[127];
}

// scatter: atomic-free; uses unfixed rowptr + blockoff (runs before prescale fix)
__global__ void scatter_kernel(const int* __restrict__ src, const int* __restrict__ dst) {
    int e = blockIdx.x * blockDim.x + threadIdx.x;
    if (e < NE) {
        int d = dst[e];
        int pos = g_rowptr[d] + g_blockoff[d >> 10] + g_tick[e];
        g_col[pos] = src[e];
    }
}

// ---------------- agg core: 16 loads in flight, pairwise fp16 -----------------
__device__ __forceinline__ void acc_pair(uint2 ua, uint2 ub,
                                         float& a0, float& a1, float& a2, float& a3) {
    __half2 px = __hadd2(*(__half2*)&ua.x, *(__half2*)&ub.x);
    __half2 py = __hadd2(*(__half2*)&ua.y, *(__half2*)&ub.y);
    float2 f0 = __half22float2(px);
    float2 f1 = __half22float2(py);
    a0 += f0.x; a1 += f0.y; a2 += f1.x; a3 += f1.y;
}
__device__ __forceinline__ void acc_one(uint2 u,
                                        float& a0, float& a1, float& a2, float& a3) {
    float2 f0 = __half22float2(*(__half2*)&u.x);
    float2 f1 = __half22float2(*(__half2*)&u.y);
    a0 += f0.x; a1 += f0.y; a2 += f1.x; a3 += f1.y;
}

__device__ __forceinline__ void agg_row(const uint2* __restrict__ G, int w, int lane,
                                        float& a0, float& a1, float& a2, float& a3) {
    int e = g_rowptr[w], end = g_rowptr[w + 1];
    const int* __restrict__ col = g_col;
    for (; e + 15 < end; e += 16) {
        int s[16];
        #pragma unroll
        for (int q = 0; q < 16; q++) s[q] = col[e + q];
        uint2 u[16];
        #pragma unroll
        for (int q = 0; q < 16; q++) u[q] = G[(size_t)s[q] * 32 + lane];
        #pragma unroll
        for (int q = 0; q < 16; q += 2) acc_pair(u[q], u[q + 1], a0, a1, a2, a3);
    }
    for (; e + 7 < end; e += 8) {
        int s0 = col[e],     s1 = col[e + 1], s2 = col[e + 2], s3 = col[e + 3];
        int s4 = col[e + 4], s5 = col[e + 5], s6 = col[e + 6], s7 = col[e + 7];
        uint2 u0 = G[(size_t)s0 * 32 + lane];
        uint2 u1 = G[(size_t)s1 * 32 + lane];
        uint2 u2 = G[(size_t)s2 * 32 + lane];
        uint2 u3 = G[(size_t)s3 * 32 + lane];
        uint2 u4 = G[(size_t)s4 * 32 + lane];
        uint2 u5 = G[(size_t)s5 * 32 + lane];
        uint2 u6 = G[(size_t)s6 * 32 + lane];
        uint2 u7 = G[(size_t)s7 * 32 + lane];
        acc_pair(u0, u1, a0, a1, a2, a3);
        acc_pair(u2, u3, a0, a1, a2, a3);
        acc_pair(u4, u5, a0, a1, a2, a3);
        acc_pair(u6, u7, a0, a1, a2, a3);
    }
    for (; e + 1 < end; e += 2) {
        int s0 = col[e], s1 = col[e + 1];
        uint2 u0 = G[(size_t)s0 * 32 + lane];
        uint2 u1 = G[(size_t)s1 * 32 + lane];
        acc_pair(u0, u1, a0, a1, a2, a3);
    }
    if (e < end) {
        uint2 u = G[(size_t)col[e] * 32 + lane];
        acc_one(u, a0, a1, a2, a3);
    }
}

// standalone agg: G (param) -> g_A
__global__ void __launch_bounds__(256) agg_kernel(const uint2* __restrict__ G) {
    int w = blockIdx.x * 8 + (threadIdx.x >> 5);
    if (w >= NN) return;
    int lane = threadIdx.x & 31;
    float a0 = 0.f, a1 = 0.f, a2 = 0.f, a3 = 0.f;
    agg_row(G, w, lane, a0, a1, a2, a3);
    float4 r; r.x = a0; r.y = a1; r.z = a2; r.w = a3;
    *(float4*)(g_A + (size_t)w * C + lane * 4) = r;
}

// ---------------- fused agg + layer-1 transform (W via __ldg, L1-resident) ----
__global__ void __launch_bounds__(256) aggt1_kernel(const float* __restrict__ W1,
                                                    const float* __restrict__ b1,
                                                    float* __restrict__ f1out) {
    __shared__ float sA[8][132];
    int t = threadIdx.x;
    int wid = t >> 5, lane = t & 31;
    int w = blockIdx.x * 8 + wid;
    if (w >= NN) return;

    float a0 = 0.f, a1 = 0.f, a2 = 0.f, a3 = 0.f;
    agg_row(g_G, w, lane, a0, a1, a2, a3);
    float4 rv; rv.x = a0; rv.y = a1; rv.z = a2; rv.w = a3;
    *(float4*)&sA[wid][lane * 4] = rv;
    __syncwarp();

    int b = lane >> 3;
    int j0 = (lane & 7) * 4;
    const float4* W4 = (const float4*)(W1 + b * 1024) + (j0 >> 2);
    const float* arow = &sA[wid][b * 32];
    float c0 = 0.f, c1 = 0.f, c2 = 0.f, c3 = 0.f;
    #pragma unroll
    for (int k = 0; k < 32; k++) {
        float a = arow[k];
        float4 w4 = __ldg(&W4[k * 8]);
        c0 = fmaf(a, w4.x, c0);
        c1 = fmaf(a, w4.y, c1);
        c2 = fmaf(a, w4.z, c2);
        c3 = fmaf(a, w4.w, c3);
    }
    float nd = g_ndst[w], ns = g_nsrc[w];
    float4 bv = __ldg((const float4*)(b1 + b * 32 + j0));
    float4 f;
    f.x = fmaf(c0, nd, bv.x);
    f.y = fmaf(c1, nd, bv.y);
    f.z = fmaf(c2, nd, bv.z);
    f.w = fmaf(c3, nd, bv.w);
    *(float4*)&f1out[((size_t)b * NN + w) * 32 + j0] = f;
    __half2 g0 = __floats2half2_rn(fmaxf(f.x, 0.f) * ns, fmaxf(f.y, 0.f) * ns);
    __half2 g1 = __floats2half2_rn(fmaxf(f.z, 0.f) * ns, fmaxf(f.w, 0.f) * ns);
    uint2 o; o.x = *(unsigned*)&g0; o.y = *(unsigned*)&g1;
    g_G2[(size_t)w * 32 + b * 8 + (j0 >> 2)] = o;
}

// ---------------- output transform (64 nodes/block, smem weights) -------------
__global__ void __launch_bounds__(256) t2_kernel(const float* __restrict__ Wout,
                                                 const float* __restrict__ bout,
                                                 float* __restrict__ outp) {
    __shared__ float Ws[4 * 1288];
    int t = threadIdx.x;
    for (int i = t; i < 4 * 1280; i += 256) {
        int b = i / 1280, r = i % 1280;
        Ws[b * 1288 + r] = Wout[i];
    }
    __syncthreads();
    int n = blockIdx.x * 64 + (t >> 2);
    int b = t & 3;
    if (n >= NN) return;
    float in[32];
    const float* arow = g_A + (size_t)n * C + b * 32;
    #pragma unroll
    for (int q = 0; q < 8; q++) {
        float4 v = *(const float4*)(arow + q * 4);
        in[q * 4] = v.x; in[q * 4 + 1] = v.y; in[q * 4 + 2] = v.z; in[q * 4 + 3] = v.w;
    }
    float acc[40];
    #pragma unroll
    for (int jq = 0; jq < 40; jq++) acc[jq] = 0.f;
    #pragma unroll
    for (int kk = 0; kk < 32; kk++) {
        float a = in[kk];
        const float* wr = &Ws[b * 1288 + kk * 40];
        #pragma unroll
        for (int q = 0; q < 10; q++) {
            float4 w = *(const float4*)(wr + q * 4);
            acc[q * 4]     = fmaf(a, w.x, acc[q * 4]);
            acc[q * 4 + 1] = fmaf(a, w.y, acc[q * 4 + 1]);
            acc[q * 4 + 2] = fmaf(a, w.z, acc[q * 4 + 2]);
            acc[q * 4 + 3] = fmaf(a, w.w, acc[q * 4 + 3]);
        }
    }
    float nd = g_ndst[n];
    const float* bb = bout + b * 40;
    float* oo = outp + ((size_t)b * NN + n) * 40;
    #pragma unroll
    for (int q = 0; q < 10; q++) {
        float4 bv = *(const float4*)(bb + q * 4);
        float4 f;
        f.x = fmaf(acc[q * 4],     nd, bv.x);
        f.y = fmaf(acc[q * 4 + 1], nd, bv.y);
        f.z = fmaf(acc[q * 4 + 2], nd, bv.z);
        f.w = fmaf(acc[q * 4 + 3], nd, bv.w);
        *(float4*)(oo + q * 4) = f;
    }
}

// ---------------- layer 0: [128 x 128] @ [128 x 128], 512 thr, f32x2 ---------
#define T0_PAD 132
#define T0_SMEM ((128 * 128 + 128 * T0_PAD) * 4)
__global__ void __launch_bounds__(512) t0_kernel(const float* __restrict__ W0,
                                                 const float* __restrict__ b0,
                                                 float* __restrict__ f0out) {
    extern __shared__ float sm[];
    float* Ws = sm;
    float* As = sm + 128 * 128;
    int t = threadIdx.x;
    int node0 = blockIdx.x * 128;
    for (int i = t; i < 4 * 128 * 32; i += 512) {
        int b = i >> 12, k = (i >> 5) & 127, j = i & 31;
        Ws[k * 128 + b * 32 + j] = W0[i];
    }
    for (int i = t; i < 128 * 128; i += 512) {
        int k = i & 127, n = i >> 7;
        int gn = node0 + n;
        As[k * T0_PAD + n] = (gn < NN) ? g_A[(size_t)gn * C + k] : 0.f;
    }
    __syncthreads();

    int cH = (t & 15) * 4;
    int nB = (t >> 4) * 4;
    unsigned long long acc[4][4];
    #pragma unroll
    for (int n = 0; n < 4; n++)
        #pragma unroll
        for (int p = 0; p < 4; p++) acc[n][p] = 0ull;

    #pragma unroll 4
    for (int k = 0; k < 128; k++) {
        float4 wa = *(const float4*)&Ws[k * 128 + cH];
        float4 wb = *(const float4*)&Ws[k * 128 + cH + 64];
        unsigned long long w0 = pk2(wa.x, wa.y), w1 = pk2(wa.z, wa.w);
        unsigned long long w2 = pk2(wb.x, wb.y), w3 = pk2(wb.z, wb.w);
        float4 A0 = *(const float4*)&As[k * T0_PAD + nB];
        float av[4] = {A0.x, A0.y, A0.z, A0.w};
        #pragma unroll
        for (int n = 0; n < 4; n++) {
            unsigned long long ap = pk2(av[n], av[n]);
            acc[n][0] = fma2(ap, w0, acc[n][0]);
            acc[n][1] = fma2(ap, w1, acc[n][1]);
            acc[n][2] = fma2(ap, w2, acc[n][2]);
            acc[n][3] = fma2(ap, w3, acc[n][3]);
        }
    }

    int bA = cH >> 5, jA = cH & 31;
    int cB = cH + 64;
    int bB = cB >> 5, jB = cB & 31;
    float4 biasA = *(const float4*)&b0[cH];
    float4 biasB = *(const float4*)&b0[cB];
    #pragma unroll
    for (int n = 0; n < 4; n++) {
        int gn = node0 + nB + n;
        if (gn >= NN) break;
        float nd = g_ndst[gn], ns = g_nsrc[gn];
        float2 p0 = upk2(acc[n][0]), p1 = upk2(acc[n][1]);
        float2 p2 = upk2(acc[n][2]), p3 = upk2(acc[n][3]);
        float4 fa, fb;
        fa.x = fmaf(p0.x, nd, biasA.x); fa.y = fmaf(p0.y, nd, biasA.y);
        fa.z = fmaf(p1.x, nd, biasA.z); fa.w = fmaf(p1.y, nd, biasA.w);
        fb.x = fmaf(p2.x, nd, biasB.x); fb.y = fmaf(p2.y, nd, biasB.y);
        fb.z = fmaf(p3.x, nd, biasB.z); fb.w = fmaf(p3.y, nd, biasB.w);
        *(float4*)&f0out[((size_t)bA * NN + gn) * 32 + jA] = fa;
        *(float4*)&f0out[((size_t)bB * NN + gn) * 32 + jB] = fb;
        __half2 ga0 = __floats2half2_rn(fmaxf(fa.x, 0.f) * ns, fmaxf(fa.y, 0.f) * ns);
        __half2 ga1 = __floats2half2_rn(fmaxf(fa.z, 0.f) * ns, fmaxf(fa.w, 0.f) * ns);
        __half2 gb0 = __floats2half2_rn(fmaxf(fb.x, 0.f) * ns, fmaxf(fb.y, 0.f) * ns);
        __half2 gb1 = __floats2half2_rn(fmaxf(fb.z, 0.f) * ns, fmaxf(fb.w, 0.f) * ns);
        uint2 oa; oa.x = *(unsigned*)&ga0; oa.y = *(unsigned*)&ga1;
        uint2 ob; ob.x = *(unsigned*)&gb0; ob.y = *(unsigned*)&gb1;
        g_G[(size_t)gn * 32 + (cH >> 2)] = oa;
        g_G[(size_t)gn * 32 + (cB >> 2)] = ob;
    }
}

// ---------------- launch --------------------------------------------------------
extern "C" void kernel_launch(void* const* d_in, const int* in_sizes, int n_in,
                              void* d_out, int out_size) {
    const float* x    = (const float*)d_in[0];
    const int*   src  = (const int*)d_in[1];
    const int*   dst  = (const int*)d_in[2];
    const float* W0   = (const float*)d_in[3];
    const float* b0   = (const float*)d_in[4];
    const float* W1   = (const float*)d_in[5];
    const float* b1   = (const float*)d_in[6];
    const float* Wout = (const float*)d_in[7];
    const float* bout = (const float*)d_in[8];

    float* outp = (float*)d_out;
    float* f0p  = outp + (size_t)4 * NN * NCLS;
    float* f1p  = f0p + (size_t)4 * NN * 32;

    cudaFuncSetAttribute(t0_kernel, cudaFuncAttributeMaxDynamicSharedMemorySize, T0_SMEM);

    void* p_deg_out; cudaGetSymbolAddress(&p_deg_out, g_deg_out);
    void* p_deg_in;  cudaGetSymbolAddress(&p_deg_in,  g_deg_in);
    void* p_G;       cudaGetSymbolAddress(&p_G,       g_G);
    void* p_G2;      cudaGetSymbolAddress(&p_G2,      g_G2);
    cudaMemsetAsync(p_deg_out, 0, NN * sizeof(int));
    cudaMemsetAsync(p_deg_in,  0, NN * sizeof(int));

    int nb_edges = (NE + 255) / 256;
    int nb_agg   = (NN + 7) / 8;
    int nb_t64   = (NN + 63) / 64;
    int nb_t128  = (NN + 127) / 128;
    int nb_pre   = (NN * 32 + 255) / 256;

    degree_kernel<<<nb_edges, 256>>>(src, dst);           // 0 (writes tickets)
    scan1_kernel<<<NB_SCAN, 1024>>>();                    // 1
    scan2_kernel<<<1, 128>>>();                           // 2
    scatter_kernel<<<nb_edges, 256>>>(src, dst);          // 3 (atomic-free)
    prescale_kernel<<<nb_pre, 256>>>(x);                  // 4 (+rowptr fix)

    agg_kernel<<<nb_agg, 256>>>((const uint2*)p_G);       // layer 0: G -> g_A
    t0_kernel<<<nb_t128, 512, T0_SMEM>>>(W0, b0, f0p);    // g_A -> f0, g_G
    aggt1_kernel<<<nb_agg, 256>>>(W1, b1, f1p);           // G -> f1, G2 (fused)
    agg_kernel<<<nb_agg, 256>>>((const uint2*)p_G2);      // layer 2: G2 -> g_A
    t2_kernel<<<nb_t64, 256>>>(Wout, bout, outp);         // g_A -> logits
}